// round 1
// baseline (speedup 1.0000x reference)
#include <cuda_runtime.h>
#include <cuda_bf16.h>
#include <math_constants.h>

// ---------------------------------------------------------------------------
// MultiHeadGATLayer: z = h @ W (per head); e = leaky_relu(a_src.z[src] + a_dst.z[dst]);
// segment-softmax over dst; out[dst] += alpha * z[src]; concat heads.
// ---------------------------------------------------------------------------

constexpr int NN = 50000;   // nodes
constexpr int NE = 800000;  // edges
constexpr int ID = 256;     // in dim
constexpr int OD = 64;      // out dim per head
constexpr int NH = 4;       // heads

// ---------------- device scratch (no allocations allowed) ------------------
__device__ float g_z[NN * NH * OD];     // projected features, layout [(n*NH+h)*OD + o]
__device__ float g_esrc[NN * NH];       // a_src . z[n,h]
__device__ float g_edst[NN * NH];       // a_dst . z[n,h]
__device__ float g_m[NN * NH];          // segment max
__device__ float g_denom[NN * NH];      // segment sum of exp
__device__ float g_e[NE * NH];          // edge logits -> exp values

// ---------------------------------------------------------------------------
// init: zero output + denom, set segment max to -inf
// ---------------------------------------------------------------------------
__global__ void k_init(float* __restrict__ out) {
    int i = blockIdx.x * blockDim.x + threadIdx.x;
    const int total = NN * NH * OD;          // 12.8M (== out elems)
    if (i < total) out[i] = 0.0f;
    if (i < NN * NH) {
        g_m[i] = -CUDART_INF_F;
        g_denom[i] = 0.0f;
    }
}

// ---------------------------------------------------------------------------
// GEMM: z[(n*NH+head)*OD + o] = sum_k h[n][k] * W[head][k][o]
// classic smem-tiled fp32: BM=128, BN=64(=OD), BK=32, 256 threads, 8x4 microtile
// ---------------------------------------------------------------------------
__global__ void k_gemm(const float* __restrict__ hp, const float* __restrict__ Wp) {
    constexpr int BM = 128, BK = 32;
    const int head = blockIdx.y;
    const int row0 = blockIdx.x * BM;
    const int tid  = threadIdx.x;
    const int tx = tid & 15;   // col group: 16 groups x 4 cols = 64
    const int ty = tid >> 4;   // row group: 16 groups x 8 rows = 128

    __shared__ float As[BM][BK];   // 16 KB
    __shared__ float Bs[BK][OD];   // 8 KB

    const float* Wh = Wp + head * ID * OD;
    float acc[8][4] = {};

    for (int kk = 0; kk < ID; kk += BK) {
        // load A tile: 128x32 floats = 1024 float4, 4 per thread, coalesced
        #pragma unroll
        for (int i = 0; i < 4; i++) {
            int lin = tid + i * 256;       // 0..1023
            int r   = lin >> 3;            // 0..127
            int kg  = lin & 7;             // 0..7
            int grow = row0 + r;
            float4 v = (grow < NN)
                ? *reinterpret_cast<const float4*>(hp + (size_t)grow * ID + kk + kg * 4)
                : make_float4(0.f, 0.f, 0.f, 0.f);
            *reinterpret_cast<float4*>(&As[r][kg * 4]) = v;
        }
        // load B tile: 32x64 floats = 512 float4, 2 per thread
        #pragma unroll
        for (int i = 0; i < 2; i++) {
            int lin = tid + i * 256;       // 0..511
            int r   = lin >> 4;            // 0..31
            int cg  = lin & 15;            // 0..15
            *reinterpret_cast<float4*>(&Bs[r][cg * 4]) =
                *reinterpret_cast<const float4*>(Wh + (size_t)(kk + r) * OD + cg * 4);
        }
        __syncthreads();

        #pragma unroll
        for (int k = 0; k < BK; k++) {
            float4 b = *reinterpret_cast<float4*>(&Bs[k][tx * 4]);
            #pragma unroll
            for (int rr = 0; rr < 8; rr++) {
                float a = As[ty * 8 + rr][k];
                acc[rr][0] = fmaf(a, b.x, acc[rr][0]);
                acc[rr][1] = fmaf(a, b.y, acc[rr][1]);
                acc[rr][2] = fmaf(a, b.z, acc[rr][2]);
                acc[rr][3] = fmaf(a, b.w, acc[rr][3]);
            }
        }
        __syncthreads();
    }

    #pragma unroll
    for (int rr = 0; rr < 8; rr++) {
        int grow = row0 + ty * 8 + rr;
        if (grow < NN) {
            float4 v = make_float4(acc[rr][0], acc[rr][1], acc[rr][2], acc[rr][3]);
            *reinterpret_cast<float4*>(&g_z[((size_t)grow * NH + head) * OD + tx * 4]) = v;
        }
    }
}

// ---------------------------------------------------------------------------
// per-(node,head) attention logits: e_src = z . a_src, e_dst = z . a_dst
// one warp per (n,h) row of 64 floats
// ---------------------------------------------------------------------------
__global__ void k_logits(const float* __restrict__ a_src, const float* __restrict__ a_dst) {
    int wg   = (blockIdx.x * blockDim.x + threadIdx.x) >> 5;
    int lane = threadIdx.x & 31;
    if (wg >= NN * NH) return;
    int hh = wg & (NH - 1);
    const float* zr = g_z + (size_t)wg * OD;
    float z0 = zr[lane], z1 = zr[lane + 32];
    float s = z0 * a_src[hh * OD + lane] + z1 * a_src[hh * OD + lane + 32];
    float d = z0 * a_dst[hh * OD + lane] + z1 * a_dst[hh * OD + lane + 32];
    #pragma unroll
    for (int off = 16; off; off >>= 1) {
        s += __shfl_xor_sync(0xFFFFFFFFu, s, off);
        d += __shfl_xor_sync(0xFFFFFFFFu, d, off);
    }
    if (lane == 0) { g_esrc[wg] = s; g_edst[wg] = d; }
}

// float atomic max via sign-split int/uint trick (IEEE monotone)
__device__ __forceinline__ void atomicMaxF(float* addr, float v) {
    int bits = __float_as_int(v);
    if (bits >= 0) atomicMax(reinterpret_cast<int*>(addr), bits);
    else           atomicMin(reinterpret_cast<unsigned int*>(addr), (unsigned int)bits);
}

// ---------------------------------------------------------------------------
// edge pass 1: e = leaky_relu(e_src[src] + e_dst[dst]); segment max over dst
// one thread per (edge, head)
// ---------------------------------------------------------------------------
__global__ void k_edge_max(const int* __restrict__ src, const int* __restrict__ dst) {
    int idx = blockIdx.x * blockDim.x + threadIdx.x;
    if (idx >= NE * NH) return;
    int hh = idx & (NH - 1);
    int e  = idx >> 2;
    int s = src[e], d = dst[e];
    float x = g_esrc[s * NH + hh] + g_edst[d * NH + hh];
    x = (x > 0.f) ? x : 0.01f * x;
    g_e[idx] = x;
    atomicMaxF(&g_m[d * NH + hh], x);
}

// ---------------------------------------------------------------------------
// edge pass 2: e_exp = exp(e - m[dst]); segment sum over dst
// ---------------------------------------------------------------------------
__global__ void k_edge_exp(const int* __restrict__ dst) {
    int idx = blockIdx.x * blockDim.x + threadIdx.x;
    if (idx >= NE * NH) return;
    int hh = idx & (NH - 1);
    int e  = idx >> 2;
    int d  = dst[e];
    float v = expf(g_e[idx] - g_m[d * NH + hh]);
    g_e[idx] = v;
    atomicAdd(&g_denom[d * NH + hh], v);
}

// ---------------------------------------------------------------------------
// edge pass 3: out[dst, h*64+o] += (e_exp/denom[dst,h]) * z[src, h, o]
// one warp per (edge, head): 64 floats, 2 per lane
// ---------------------------------------------------------------------------
__global__ void k_aggregate(const int* __restrict__ src, const int* __restrict__ dst,
                            float* __restrict__ out) {
    int wg   = (blockIdx.x * blockDim.x + threadIdx.x) >> 5;
    int lane = threadIdx.x & 31;
    if (wg >= NE * NH) return;
    int hh = wg & (NH - 1);
    int e  = wg >> 2;
    int s = src[e], d = dst[e];
    float coef = g_e[wg] / g_denom[d * NH + hh];
    const float* zp = g_z + ((size_t)s * NH + hh) * OD;
    float* op = out + (size_t)d * (NH * OD) + hh * OD;
    atomicAdd(op + lane,      coef * zp[lane]);
    atomicAdd(op + lane + 32, coef * zp[lane + 32]);
}

// ---------------------------------------------------------------------------
// launch
// inputs (metadata order): h[f32], src[i32], dst[i32], W[f32], a_src[f32], a_dst[f32]
// output: f32 [NN, NH*OD]
// ---------------------------------------------------------------------------
extern "C" void kernel_launch(void* const* d_in, const int* in_sizes, int n_in,
                              void* d_out, int out_size) {
    const float* hp    = (const float*)d_in[0];
    const int*   src   = (const int*)d_in[1];
    const int*   dst   = (const int*)d_in[2];
    const float* Wp    = (const float*)d_in[3];
    const float* a_src = (const float*)d_in[4];
    const float* a_dst = (const float*)d_in[5];
    float* out = (float*)d_out;

    // init output + softmax state
    {
        int total = NN * NH * OD;
        k_init<<<(total + 255) / 256, 256>>>(out);
    }
    // projection GEMM
    {
        dim3 grid((NN + 127) / 128, NH);
        k_gemm<<<grid, 256>>>(hp, Wp);
    }
    // per-(n,h) logit dots
    {
        int warps = NN * NH;
        int threads = warps * 32;
        k_logits<<<(threads + 255) / 256, 256>>>(a_src, a_dst);
    }
    // edge pass 1: logits + segment max
    {
        int total = NE * NH;
        k_edge_max<<<(total + 255) / 256, 256>>>(src, dst);
    }
    // edge pass 2: exp + segment sum
    {
        int total = NE * NH;
        k_edge_exp<<<(total + 255) / 256, 256>>>(dst);
    }
    // edge pass 3: weighted scatter aggregation
    {
        long long threads = (long long)NE * NH * 32;
        int blocks = (int)((threads + 255) / 256);
        k_aggregate<<<blocks, 256>>>(src, dst, out);
    }
}

// round 3
// speedup vs baseline: 1.6426x; 1.6426x over previous
#include <cuda_runtime.h>
#include <cuda_bf16.h>
#include <math_constants.h>

// ---------------------------------------------------------------------------
// MultiHeadGATLayer, CSR-gather formulation:
//   z = h @ W (per head); e = leaky_relu(a_src.z[src] + a_dst.z[dst]);
//   segment-softmax over dst; out[dst] = sum alpha * z[src]; concat heads.
// dst-CSR built per launch; softmax + aggregation fused into one
// warp-per-destination kernel with NO atomics in the hot path.
// ---------------------------------------------------------------------------

constexpr int NN = 50000;   // nodes
constexpr int NE = 800000;  // edges
constexpr int ID = 256;     // in dim
constexpr int OD = 64;      // out dim per head
constexpr int NH = 4;       // heads

// ---------------- device scratch (no allocations allowed) ------------------
__device__ float g_z[NN * NH * OD];     // projected features [(n*NH+h)*OD + o]
__device__ float g_esrc[NN * NH];       // a_src . z[n,h]
__device__ float g_edst[NN * NH];       // a_dst . z[n,h]
__device__ int   g_deg[NN];             // in-degree histogram
__device__ int   g_rowptr[NN + 1];      // CSR row pointers (by dst)
__device__ int   g_cursor[NN];          // scatter cursors
__device__ int   g_csr_src[NE];         // src node id per CSR slot

// ---------------------------------------------------------------------------
// init: zero degree histogram + cursors (graph replays need this every launch)
// ---------------------------------------------------------------------------
__global__ void k_init() {
    int i = blockIdx.x * blockDim.x + threadIdx.x;
    if (i < NN) { g_deg[i] = 0; g_cursor[i] = 0; }
}

// ---------------------------------------------------------------------------
// GEMM: z[(n*NH+head)*OD + o] = sum_k h[n][k] * W[head][k][o]
// smem-tiled fp32: BM=128, BN=64(=OD), BK=32, 256 threads, 8x4 microtile
// ---------------------------------------------------------------------------
__global__ void k_gemm(const float* __restrict__ hp, const float* __restrict__ Wp) {
    constexpr int BM = 128, BK = 32;
    const int head = blockIdx.y;
    const int row0 = blockIdx.x * BM;
    const int tid  = threadIdx.x;
    const int tx = tid & 15;   // 16 col groups x 4 cols = 64
    const int ty = tid >> 4;   // 16 row groups x 8 rows = 128

    __shared__ float As[BM][BK];   // 16 KB
    __shared__ float Bs[BK][OD];   // 8 KB

    const float* Wh = Wp + head * ID * OD;
    float acc[8][4] = {};

    for (int kk = 0; kk < ID; kk += BK) {
        #pragma unroll
        for (int i = 0; i < 4; i++) {
            int lin = tid + i * 256;       // 0..1023
            int r   = lin >> 3;
            int kg  = lin & 7;
            int grow = row0 + r;
            float4 v = (grow < NN)
                ? *reinterpret_cast<const float4*>(hp + (size_t)grow * ID + kk + kg * 4)
                : make_float4(0.f, 0.f, 0.f, 0.f);
            *reinterpret_cast<float4*>(&As[r][kg * 4]) = v;
        }
        #pragma unroll
        for (int i = 0; i < 2; i++) {
            int lin = tid + i * 256;       // 0..511
            int r   = lin >> 4;
            int cg  = lin & 15;
            *reinterpret_cast<float4*>(&Bs[r][cg * 4]) =
                *reinterpret_cast<const float4*>(Wh + (size_t)(kk + r) * OD + cg * 4);
        }
        __syncthreads();

        #pragma unroll
        for (int k = 0; k < BK; k++) {
            float4 b = *reinterpret_cast<float4*>(&Bs[k][tx * 4]);
            #pragma unroll
            for (int rr = 0; rr < 8; rr++) {
                float a = As[ty * 8 + rr][k];
                acc[rr][0] = fmaf(a, b.x, acc[rr][0]);
                acc[rr][1] = fmaf(a, b.y, acc[rr][1]);
                acc[rr][2] = fmaf(a, b.z, acc[rr][2]);
                acc[rr][3] = fmaf(a, b.w, acc[rr][3]);
            }
        }
        __syncthreads();
    }

    #pragma unroll
    for (int rr = 0; rr < 8; rr++) {
        int grow = row0 + ty * 8 + rr;
        if (grow < NN) {
            float4 v = make_float4(acc[rr][0], acc[rr][1], acc[rr][2], acc[rr][3]);
            *reinterpret_cast<float4*>(&g_z[((size_t)grow * NH + head) * OD + tx * 4]) = v;
        }
    }
}

// ---------------------------------------------------------------------------
// per-(node,head) attention logits: e_src = z . a_src, e_dst = z . a_dst
// one warp per (n,h) row of 64 floats
// ---------------------------------------------------------------------------
__global__ void k_logits(const float* __restrict__ a_src, const float* __restrict__ a_dst) {
    int wg   = (blockIdx.x * blockDim.x + threadIdx.x) >> 5;
    int lane = threadIdx.x & 31;
    if (wg >= NN * NH) return;
    int hh = wg & (NH - 1);
    const float* zr = g_z + (size_t)wg * OD;
    float z0 = zr[lane], z1 = zr[lane + 32];
    float s = z0 * a_src[hh * OD + lane] + z1 * a_src[hh * OD + lane + 32];
    float d = z0 * a_dst[hh * OD + lane] + z1 * a_dst[hh * OD + lane + 32];
    #pragma unroll
    for (int off = 16; off; off >>= 1) {
        s += __shfl_xor_sync(0xFFFFFFFFu, s, off);
        d += __shfl_xor_sync(0xFFFFFFFFu, d, off);
    }
    if (lane == 0) { g_esrc[wg] = s; g_edst[wg] = d; }
}

// ---------------------------------------------------------------------------
// CSR build step 1: in-degree histogram over dst
// ---------------------------------------------------------------------------
__global__ void k_hist(const int* __restrict__ dst) {
    int e = blockIdx.x * blockDim.x + threadIdx.x;
    if (e < NE) atomicAdd(&g_deg[dst[e]], 1);
}

// ---------------------------------------------------------------------------
// CSR build step 2: exclusive scan of degrees -> rowptr (single block)
// ---------------------------------------------------------------------------
__global__ void k_scan() {
    __shared__ int s[1024];
    __shared__ int carry;
    const int tid = threadIdx.x;
    if (tid == 0) carry = 0;
    __syncthreads();
    for (int base = 0; base < NN; base += 1024) {
        int i = base + tid;
        int v = (i < NN) ? g_deg[i] : 0;
        s[tid] = v;
        __syncthreads();
        // Hillis-Steele inclusive scan
        #pragma unroll
        for (int off = 1; off < 1024; off <<= 1) {
            int t = (tid >= off) ? s[tid - off] : 0;
            __syncthreads();
            s[tid] += t;
            __syncthreads();
        }
        if (i < NN) g_rowptr[i] = carry + s[tid] - v;   // exclusive
        __syncthreads();                                // all read carry first
        if (tid == 1023) carry += s[1023];
        __syncthreads();
    }
    if (tid == 0) g_rowptr[NN] = carry;                 // == NE
}

// ---------------------------------------------------------------------------
// CSR build step 3: scatter src ids into CSR slots
// ---------------------------------------------------------------------------
__global__ void k_scatter(const int* __restrict__ src, const int* __restrict__ dst) {
    int e = blockIdx.x * blockDim.x + threadIdx.x;
    if (e >= NE) return;
    int d = dst[e];
    int pos = atomicAdd(&g_cursor[d], 1);
    g_csr_src[g_rowptr[d] + pos] = src[e];
}

__device__ __forceinline__ float lrelu(float x) {
    return (x > 0.f) ? x : 0.01f * x;
}

// ---------------------------------------------------------------------------
// fused softmax + aggregation: one warp per destination node, no atomics.
// pass 1: segment max per head; pass 2: exp-sum; pass 3: serial edge loop,
// acc[8] registers per lane hold the 256-float output row.
// ---------------------------------------------------------------------------
__global__ void __launch_bounds__(256) k_agg(float* __restrict__ out) {
    const int row  = blockIdx.x * 8 + (threadIdx.x >> 5);
    const int lane = threadIdx.x & 31;
    if (row >= NN) return;
    const int start = g_rowptr[row];
    const int end   = g_rowptr[row + 1];

    const float4 ed = *reinterpret_cast<const float4*>(g_edst + row * NH);

    // ---- pass 1: max per head over incoming edges ----
    float m0 = -CUDART_INF_F, m1 = m0, m2 = m0, m3 = m0;
    for (int i = start + lane; i < end; i += 32) {
        int s = g_csr_src[i];
        float4 es = *reinterpret_cast<const float4*>(g_esrc + s * NH);
        m0 = fmaxf(m0, lrelu(es.x + ed.x));
        m1 = fmaxf(m1, lrelu(es.y + ed.y));
        m2 = fmaxf(m2, lrelu(es.z + ed.z));
        m3 = fmaxf(m3, lrelu(es.w + ed.w));
    }
    #pragma unroll
    for (int off = 16; off; off >>= 1) {
        m0 = fmaxf(m0, __shfl_xor_sync(0xFFFFFFFFu, m0, off));
        m1 = fmaxf(m1, __shfl_xor_sync(0xFFFFFFFFu, m1, off));
        m2 = fmaxf(m2, __shfl_xor_sync(0xFFFFFFFFu, m2, off));
        m3 = fmaxf(m3, __shfl_xor_sync(0xFFFFFFFFu, m3, off));
    }

    // ---- pass 2: sum of exp ----
    float s0 = 0.f, s1 = 0.f, s2 = 0.f, s3 = 0.f;
    for (int i = start + lane; i < end; i += 32) {
        int s = g_csr_src[i];
        float4 es = *reinterpret_cast<const float4*>(g_esrc + s * NH);
        s0 += __expf(lrelu(es.x + ed.x) - m0);
        s1 += __expf(lrelu(es.y + ed.y) - m1);
        s2 += __expf(lrelu(es.z + ed.z) - m2);
        s3 += __expf(lrelu(es.w + ed.w) - m3);
    }
    #pragma unroll
    for (int off = 16; off; off >>= 1) {
        s0 += __shfl_xor_sync(0xFFFFFFFFu, s0, off);
        s1 += __shfl_xor_sync(0xFFFFFFFFu, s1, off);
        s2 += __shfl_xor_sync(0xFFFFFFFFu, s2, off);
        s3 += __shfl_xor_sync(0xFFFFFFFFu, s3, off);
    }
    const float i0 = 1.f / s0, i1 = 1.f / s1, i2 = 1.f / s2, i3 = 1.f / s3;

    // ---- pass 3: weighted gather-accumulate (serial over edges, full warp) ----
    float acc[8] = {};
    for (int i = start; i < end; i++) {
        int s = g_csr_src[i];                                    // broadcast
        float4 es = *reinterpret_cast<const float4*>(g_esrc + s * NH);
        float a0 = __expf(lrelu(es.x + ed.x) - m0) * i0;
        float a1 = __expf(lrelu(es.y + ed.y) - m1) * i1;
        float a2 = __expf(lrelu(es.z + ed.z) - m2) * i2;
        float a3 = __expf(lrelu(es.w + ed.w) - m3) * i3;
        const float* zp = g_z + (size_t)s * (NH * OD);
        acc[0] = fmaf(a0, zp[lane      ], acc[0]);
        acc[1] = fmaf(a0, zp[lane +  32], acc[1]);
        acc[2] = fmaf(a1, zp[lane +  64], acc[2]);
        acc[3] = fmaf(a1, zp[lane +  96], acc[3]);
        acc[4] = fmaf(a2, zp[lane + 128], acc[4]);
        acc[5] = fmaf(a2, zp[lane + 160], acc[5]);
        acc[6] = fmaf(a3, zp[lane + 192], acc[6]);
        acc[7] = fmaf(a3, zp[lane + 224], acc[7]);
    }

    float* op = out + (size_t)row * (NH * OD);
    #pragma unroll
    for (int j = 0; j < 8; j++) op[lane + 32 * j] = acc[j];     // zero-degree rows -> 0
}

// ---------------------------------------------------------------------------
// launch — inputs (metadata order): h[f32], src[i32], dst[i32], W[f32],
//          a_src[f32], a_dst[f32]; output f32 [NN, NH*OD]
// ---------------------------------------------------------------------------
extern "C" void kernel_launch(void* const* d_in, const int* in_sizes, int n_in,
                              void* d_out, int out_size) {
    const float* hp    = (const float*)d_in[0];
    const int*   src   = (const int*)d_in[1];
    const int*   dst   = (const int*)d_in[2];
    const float* Wp    = (const float*)d_in[3];
    const float* a_src = (const float*)d_in[4];
    const float* a_dst = (const float*)d_in[5];
    float* out = (float*)d_out;

    k_init<<<(NN + 255) / 256, 256>>>();

    {
        dim3 grid((NN + 127) / 128, NH);
        k_gemm<<<grid, 256>>>(hp, Wp);
    }
    {
        int threads = NN * NH * 32;
        k_logits<<<(threads + 255) / 256, 256>>>(a_src, a_dst);
    }
    k_hist<<<(NE + 255) / 256, 256>>>(dst);
    k_scan<<<1, 1024>>>();
    k_scatter<<<(NE + 255) / 256, 256>>>(src, dst);
    {
        int blocks = (NN + 7) / 8;   // 8 warps per block, one warp per dst node
        k_agg<<<blocks, 256>>>(out);
    }
}